// round 9
// baseline (speedup 1.0000x reference)
#include <cuda_runtime.h>

// Problem constants
#define IN_SZ   8192
#define OUT_SZ  8192
#define OUT4    (OUT_SZ / 4)            // 2048 float4 columns
// sigmoid(2.0)
#define SIG_TAU 0.8807970779778823f

// Tiling (proven R8 shape): 1024 blocks x 256 threads; each block covers
// 32 float4 columns x 512 rows; 8 warps split the rows (64 rows each).
#define THREADS        256
#define WARPS          8
#define SLAB_COLS4     32               // float4 columns per block (one per lane)
#define NSLAB          (OUT4 / SLAB_COLS4)        // 64 column slabs
#define RGROUPS        16               // row groups (split-K depth)
#define ROWS_PER_BLOCK (IN_SZ / RGROUPS)          // 512
#define ROWS_PER_WARP  (ROWS_PER_BLOCK / WARPS)   // 64

// Deterministic split-K scratch: 16 x 2048 float4 = 512 KB.
__device__ float4 g_partial4[RGROUPS * OUT4];

// K1: pure GEMV partials — reads W (256 MB, homogeneous read stream).
// Summation tree identical to R8 (warp 64-row serial + fixed 8-warp combine).
__global__ __launch_bounds__(THREADS, 1)
void ostl_gemv_kernel(const float* __restrict__ x,
                      const float* __restrict__ W)
{
    __shared__ float  sx[ROWS_PER_BLOCK];              // 2 KB
    __shared__ float4 sacc[WARPS][SLAB_COLS4];         // 4 KB

    const int lane = threadIdx.x & 31;
    const int w    = threadIdx.x >> 5;
    const int c    = blockIdx.x * SLAB_COLS4 + lane;
    const int rg0  = blockIdx.y * ROWS_PER_BLOCK;

    for (int i = threadIdx.x; i < ROWS_PER_BLOCK; i += THREADS)
        sx[i] = x[rg0 + i];
    __syncthreads();

    const float4* __restrict__ W4 = (const float4*)W;

    float4 acc = make_float4(0.f, 0.f, 0.f, 0.f);
    const int rbase = w * ROWS_PER_WARP;
    int idx = (rg0 + rbase) * OUT4 + c;                // max ~16.7M -> fits int

    #pragma unroll 4
    for (int r = 0; r < ROWS_PER_WARP; ++r, idx += OUT4) {
        const float xi = sx[rbase + r];
        const float4 wv = W4[idx];
        acc.x = fmaf(xi, wv.x, acc.x);
        acc.y = fmaf(xi, wv.y, acc.y);
        acc.z = fmaf(xi, wv.z, acc.z);
        acc.w = fmaf(xi, wv.w, acc.w);
    }

    sacc[w][lane] = acc;
    __syncthreads();

    if (w == 0) {
        float4 a = sacc[0][lane];
        #pragma unroll
        for (int t = 1; t < WARPS; ++t) {
            const float4 b = sacc[t][lane];
            a.x += b.x; a.y += b.y; a.z += b.z; a.w += b.w;
        }
        g_partial4[blockIdx.y * OUT4 + c] = a;
    }
}

// K2: pure eligibility-trace stream — Jout = SIG_TAU*J + x[row]
// (256 MB read + 256 MB write, homogeneous triad).
__global__ __launch_bounds__(THREADS, 1)
void ostl_jstream_kernel(const float* __restrict__ x,
                         const float* __restrict__ J,
                         float* __restrict__ Jout)
{
    __shared__ float sx[ROWS_PER_BLOCK];

    const int lane = threadIdx.x & 31;
    const int w    = threadIdx.x >> 5;
    const int c    = blockIdx.x * SLAB_COLS4 + lane;
    const int rg0  = blockIdx.y * ROWS_PER_BLOCK;

    for (int i = threadIdx.x; i < ROWS_PER_BLOCK; i += THREADS)
        sx[i] = x[rg0 + i];
    __syncthreads();

    const float4* __restrict__ J4 = (const float4*)J;
    float4*       __restrict__ O4 = (float4*)Jout;

    const int rbase = w * ROWS_PER_WARP;
    int idx = (rg0 + rbase) * OUT4 + c;

    #pragma unroll 4
    for (int r = 0; r < ROWS_PER_WARP; ++r, idx += OUT4) {
        const float xi = sx[rbase + r];
        const float4 jv = J4[idx];
        float4 o;
        o.x = fmaf(SIG_TAU, jv.x, xi);
        o.y = fmaf(SIG_TAU, jv.y, xi);
        o.z = fmaf(SIG_TAU, jv.z, xi);
        o.w = fmaf(SIG_TAU, jv.w, xi);
        O4[idx] = o;
    }
}

// Epilogue: reduce 16 x 2048 float4 partials (512 KB, L2-warm right after K1),
// LIF update, write u_out and s. Runs on a SIDE stream overlapped with K2.
#define EPI_TPB   32
#define EPI_GRID  (OUT4 / EPI_TPB)     // 64 blocks
__global__ __launch_bounds__(EPI_TPB, 1)
void ostl_epilogue_kernel(const float* __restrict__ u,
                          float* __restrict__ out_u,
                          float* __restrict__ out_s)
{
    const int c = blockIdx.x * EPI_TPB + threadIdx.x;

    float4 a = make_float4(0.f, 0.f, 0.f, 0.f);
    #pragma unroll
    for (int k = 0; k < RGROUPS; ++k) {                 // 16 independent loads
        const float4 p = g_partial4[k * OUT4 + c];
        a.x += p.x; a.y += p.y; a.z += p.z; a.w += p.w;
    }

    const float4 uu = ((const float4*)u)[c];
    float4 uo, so;
    {
        float un;
        un = fmaf(SIG_TAU, uu.x, a.x); so.x = (un - 1.0f) > 0.f ? 1.f : 0.f; uo.x = un - so.x;
        un = fmaf(SIG_TAU, uu.y, a.y); so.y = (un - 1.0f) > 0.f ? 1.f : 0.f; uo.y = un - so.y;
        un = fmaf(SIG_TAU, uu.z, a.z); so.z = (un - 1.0f) > 0.f ? 1.f : 0.f; uo.z = un - so.z;
        un = fmaf(SIG_TAU, uu.w, a.w); so.w = (un - 1.0f) > 0.f ? 1.f : 0.f; uo.w = un - so.w;
    }
    ((float4*)out_u)[c] = uo;
    ((float4*)out_s)[c] = so;
}

extern "C" void kernel_launch(void* const* d_in, const int* in_sizes, int n_in,
                              void* d_out, int out_size)
{
    const float* x = (const float*)d_in[0];
    const float* u = (const float*)d_in[1];
    const float* J = (const float*)d_in[2];
    const float* W = (const float*)d_in[3];

    float* out   = (float*)d_out;
    float* out_u = out;                                   // [0, 8192)
    float* out_J = out + OUT_SZ;                          // [8192, 8192+64M)
    float* out_s = out + OUT_SZ + (size_t)IN_SZ * OUT_SZ; // last 8192

    // Side stream + events for capture-legal fork-join (created per call; the
    // harness calls kernel_launch only a couple of times, so no churn).
    cudaStream_t s_side;
    cudaEvent_t  e_fork, e_join;
    cudaStreamCreateWithFlags(&s_side, cudaStreamNonBlocking);
    cudaEventCreateWithFlags(&e_fork, cudaEventDisableTiming);
    cudaEventCreateWithFlags(&e_join, cudaEventDisableTiming);

    dim3 grid(NSLAB, RGROUPS);                            // 64 x 16 = 1024 blocks

    // K1: GEMV partials (capture stream)
    ostl_gemv_kernel<<<grid, THREADS>>>(x, W);

    // Fork: epilogue on side stream, depends only on K1
    cudaEventRecord(e_fork, 0);
    cudaStreamWaitEvent(s_side, e_fork, 0);
    ostl_epilogue_kernel<<<EPI_GRID, EPI_TPB, 0, s_side>>>(u, out_u, out_s);

    // K2: J-trace stream, overlaps the epilogue (disjoint outputs)
    ostl_jstream_kernel<<<grid, THREADS>>>(x, J, out_J);

    // Join side stream back into the capture stream
    cudaEventRecord(e_join, s_side);
    cudaStreamWaitEvent(0, e_join, 0);
}

// round 10
// speedup vs baseline: 1.1303x; 1.1303x over previous
#include <cuda_runtime.h>

// Problem constants
#define IN_SZ   8192
#define OUT_SZ  8192
#define OUT4    (OUT_SZ / 4)            // 2048 float4 columns
// sigmoid(2.0)
#define SIG_TAU 0.8807970779778823f

// Main-kernel tiling — FROZEN R8 config (121.2us, 6.35 TB/s). Do not touch.
#define THREADS        256
#define WARPS          8
#define SLAB_COLS4     32               // float4 columns per block (one per lane)
#define NSLAB          (OUT4 / SLAB_COLS4)        // 64 column slabs
#define RGROUPS        16               // row groups (split-K depth)
#define ROWS_PER_BLOCK (IN_SZ / RGROUPS)          // 512
#define ROWS_PER_WARP  (ROWS_PER_BLOCK / WARPS)   // 64

// Deterministic split-K scratch: 16 x 2048 float4 = 512 KB.
__device__ float4 g_partial4[RGROUPS * OUT4];

__global__ __launch_bounds__(THREADS, 1)
void ostl_main_kernel(const float* __restrict__ x,
                      const float* __restrict__ J,
                      const float* __restrict__ W,
                      float* __restrict__ Jout)
{
    __shared__ float  sx[ROWS_PER_BLOCK];              // 2 KB
    __shared__ float4 sacc[WARPS][SLAB_COLS4];         // 4 KB

    const int lane = threadIdx.x & 31;
    const int w    = threadIdx.x >> 5;                 // warp 0..7
    const int c    = blockIdx.x * SLAB_COLS4 + lane;   // float4 column
    const int rg0  = blockIdx.y * ROWS_PER_BLOCK;      // block row base

    for (int i = threadIdx.x; i < ROWS_PER_BLOCK; i += THREADS)
        sx[i] = x[rg0 + i];
    __syncthreads();

    const float4* __restrict__ W4 = (const float4*)W;
    const float4* __restrict__ J4 = (const float4*)J;
    float4*       __restrict__ O4 = (float4*)Jout;

    float4 acc = make_float4(0.f, 0.f, 0.f, 0.f);
    const int rbase = w * ROWS_PER_WARP;               // warp's rows within block
    int idx = (rg0 + rbase) * OUT4 + c;                // max ~16.7M -> fits int

    #pragma unroll 4
    for (int r = 0; r < ROWS_PER_WARP; ++r, idx += OUT4) {
        const float xi = sx[rbase + r];
        const float4 wv = W4[idx];
        const float4 jv = J4[idx];

        acc.x = fmaf(xi, wv.x, acc.x);
        acc.y = fmaf(xi, wv.y, acc.y);
        acc.z = fmaf(xi, wv.z, acc.z);
        acc.w = fmaf(xi, wv.w, acc.w);

        float4 o;
        o.x = fmaf(SIG_TAU, jv.x, xi);
        o.y = fmaf(SIG_TAU, jv.y, xi);
        o.z = fmaf(SIG_TAU, jv.z, xi);
        o.w = fmaf(SIG_TAU, jv.w, xi);
        O4[idx] = o;
    }

    // In-block cross-warp reduction in FIXED warp order -> deterministic.
    sacc[w][lane] = acc;
    __syncthreads();

    if (w == 0) {
        float4 a = sacc[0][lane];
        #pragma unroll
        for (int t = 1; t < WARPS; ++t) {
            const float4 b = sacc[t][lane];
            a.x += b.x; a.y += b.y; a.z += b.z; a.w += b.w;
        }
        g_partial4[blockIdx.y * OUT4 + c] = a;
    }
}

// Epilogue (PDL secondary): pre-load u (main never writes it), then
// cudaGridDependencySynchronize() before touching the partials.
#define EPI_TPB   32
#define EPI_GRID  (OUT4 / EPI_TPB)     // 64 blocks
__global__ __launch_bounds__(EPI_TPB, 1)
void ostl_epilogue_kernel(const float* __restrict__ u,
                          float* __restrict__ out_u,
                          float* __restrict__ out_s)
{
    const int c = blockIdx.x * EPI_TPB + threadIdx.x;   // float4 column

    // Safe before the dependency sync: u is an input, untouched by main.
    const float4 uu = ((const float4*)u)[c];

    // Wait for the primary (main kernel) to complete.
    cudaGridDependencySynchronize();

    float4 a = make_float4(0.f, 0.f, 0.f, 0.f);
    #pragma unroll
    for (int k = 0; k < RGROUPS; ++k) {                 // 16 independent loads
        const float4 p = g_partial4[k * OUT4 + c];      // L2-warm 512B lines
        a.x += p.x; a.y += p.y; a.z += p.z; a.w += p.w;
    }

    float4 uo, so;
    {
        float un;
        un = fmaf(SIG_TAU, uu.x, a.x); so.x = (un - 1.0f) > 0.f ? 1.f : 0.f; uo.x = un - so.x;
        un = fmaf(SIG_TAU, uu.y, a.y); so.y = (un - 1.0f) > 0.f ? 1.f : 0.f; uo.y = un - so.y;
        un = fmaf(SIG_TAU, uu.z, a.z); so.z = (un - 1.0f) > 0.f ? 1.f : 0.f; uo.z = un - so.z;
        un = fmaf(SIG_TAU, uu.w, a.w); so.w = (un - 1.0f) > 0.f ? 1.f : 0.f; uo.w = un - so.w;
    }
    ((float4*)out_u)[c] = uo;
    ((float4*)out_s)[c] = so;
}

extern "C" void kernel_launch(void* const* d_in, const int* in_sizes, int n_in,
                              void* d_out, int out_size)
{
    const float* x = (const float*)d_in[0];
    const float* u = (const float*)d_in[1];
    const float* J = (const float*)d_in[2];
    const float* W = (const float*)d_in[3];

    float* out   = (float*)d_out;
    float* out_u = out;                                   // [0, 8192)
    float* out_J = out + OUT_SZ;                          // [8192, 8192+64M)
    float* out_s = out + OUT_SZ + (size_t)IN_SZ * OUT_SZ; // last 8192

    dim3 grid(NSLAB, RGROUPS);                            // 64 x 16 = 1024 blocks
    ostl_main_kernel<<<grid, THREADS>>>(x, J, W, out_J);

    // PDL launch: epilogue dispatches while main drains; correctness is
    // guaranteed by cudaGridDependencySynchronize() inside the kernel.
    cudaLaunchAttribute attrs[1];
    attrs[0].id = cudaLaunchAttributeProgrammaticStreamSerialization;
    attrs[0].val.programmaticStreamSerializationAllowed = 1;

    cudaLaunchConfig_t cfg = {};
    cfg.gridDim  = dim3(EPI_GRID, 1, 1);
    cfg.blockDim = dim3(EPI_TPB, 1, 1);
    cfg.dynamicSmemBytes = 0;
    cfg.stream   = 0;
    cfg.attrs    = attrs;
    cfg.numAttrs = 1;
    cudaLaunchKernelEx(&cfg, ostl_epilogue_kernel, u, out_u, out_s);
}